// round 2
// baseline (speedup 1.0000x reference)
#include <cuda_runtime.h>
#include <math.h>

// Problem constants (fixed by the dataset)
#define N_  12288
#define F_  256
#define C_  6144
#define BMW (N_ / 32)          // bitmap words per row = 384
#define BM_TOTAL (N_ * BMW)    // 4,718,592 words = 18.9 MB

// ---- scratch (device globals; no runtime allocation allowed) ----
__device__ float    g_S [(size_t)N_ * C_];   // softmax assignments  [N, C]
__device__ float    g_T [(size_t)N_ * C_];   // logits, then A@S     [N, C]
__device__ float    g_xT[(size_t)F_ * N_];   // (x+emb)^T            [F, N]
__device__ unsigned g_bm[BM_TOTAL];          // dedup adjacency bitmap
__device__ float    g_part[8 * C_];          // partial column sums
__device__ int      g_maxbatch;

// ---------------------------------------------------------------------------
// zero scratch that must be clean each launch
// ---------------------------------------------------------------------------
__global__ void k_zero() {
    int i = blockIdx.x * blockDim.x + threadIdx.x;
    if (i < BM_TOTAL) g_bm[i] = 0u;
    if (i == 0) g_maxbatch = 0;
}

// ---------------------------------------------------------------------------
// xT[f, n] = x[n, f] + emb[f]   (tiled transpose)
// ---------------------------------------------------------------------------
__global__ void k_xT(const float* __restrict__ x, const float* __restrict__ emb) {
    __shared__ float tile[32][33];
    int f0 = blockIdx.x * 32, n0 = blockIdx.y * 32;
    int tx = threadIdx.x, ty = threadIdx.y;  // (32, 8)
    #pragma unroll
    for (int i = ty; i < 32; i += 8)
        tile[i][tx] = x[(size_t)(n0 + i) * F_ + f0 + tx] + emb[f0 + tx];
    __syncthreads();
    #pragma unroll
    for (int i = ty; i < 32; i += 8)
        g_xT[(size_t)(f0 + i) * N_ + n0 + tx] = tile[tx][i];
}

// ---------------------------------------------------------------------------
// TN GEMM: Out[i, j] = sum_k A[k, i] * B[k, j]
//   A row-major [K, M] (lda), B row-major [K, Nn] (ldb), Out [M, Nn] (ldc)
//   128x128 block tile, 16 k-step, 8x8 microtile, double-buffered smem.
//   All dims are multiples of 128 / 16 -> no bounds checks.
// ---------------------------------------------------------------------------
__global__ __launch_bounds__(256, 2)
void k_gemm_tn(const float* __restrict__ A, int lda,
               const float* __restrict__ B, int ldb,
               float* __restrict__ Cout, int ldc, int K) {
    __shared__ float As[2][16][128];
    __shared__ float Bs[2][16][128];

    const int bi = blockIdx.y * 128;   // M offset
    const int bj = blockIdx.x * 128;   // N offset
    const int tid = threadIdx.x;
    const int lk  = tid >> 5;          // 0..7 (k row within half-tile)
    const int lm  = (tid & 31) << 2;   // 0..124 (float4 column)
    const int tx  = tid & 15, ty = tid >> 4;

    const float* Ap = A + (size_t)lk * lda + bi + lm;
    const float* Bp = B + (size_t)lk * ldb + bj + lm;

    float acc[8][8];
    #pragma unroll
    for (int i = 0; i < 8; ++i)
        #pragma unroll
        for (int j = 0; j < 8; ++j) acc[i][j] = 0.f;

    // prologue: tile 0
    {
        float4 a0 = *(const float4*)(Ap);
        float4 a1 = *(const float4*)(Ap + (size_t)8 * lda);
        float4 b0 = *(const float4*)(Bp);
        float4 b1 = *(const float4*)(Bp + (size_t)8 * ldb);
        *(float4*)&As[0][lk][lm]     = a0;
        *(float4*)&As[0][lk + 8][lm] = a1;
        *(float4*)&Bs[0][lk][lm]     = b0;
        *(float4*)&Bs[0][lk + 8][lm] = b1;
    }
    __syncthreads();

    const int ntiles = K >> 4;
    for (int t = 0; t < ntiles; ++t) {
        float4 a0, a1, b0, b1;
        const bool more = (t + 1 < ntiles);
        if (more) {
            const float* Ap2 = Ap + (size_t)(t + 1) * 16 * lda;
            const float* Bp2 = Bp + (size_t)(t + 1) * 16 * ldb;
            a0 = *(const float4*)(Ap2);
            a1 = *(const float4*)(Ap2 + (size_t)8 * lda);
            b0 = *(const float4*)(Bp2);
            b1 = *(const float4*)(Bp2 + (size_t)8 * ldb);
        }
        const int buf = t & 1;
        #pragma unroll
        for (int k = 0; k < 16; ++k) {
            float4 ra0 = *(const float4*)&As[buf][k][ty * 4];
            float4 ra1 = *(const float4*)&As[buf][k][ty * 4 + 64];
            float4 rb0 = *(const float4*)&Bs[buf][k][tx * 4];
            float4 rb1 = *(const float4*)&Bs[buf][k][tx * 4 + 64];
            float av[8] = {ra0.x, ra0.y, ra0.z, ra0.w, ra1.x, ra1.y, ra1.z, ra1.w};
            float bv[8] = {rb0.x, rb0.y, rb0.z, rb0.w, rb1.x, rb1.y, rb1.z, rb1.w};
            #pragma unroll
            for (int ii = 0; ii < 8; ++ii)
                #pragma unroll
                for (int jj = 0; jj < 8; ++jj)
                    acc[ii][jj] += av[ii] * bv[jj];
        }
        if (more) {
            const int nb = buf ^ 1;
            *(float4*)&As[nb][lk][lm]     = a0;
            *(float4*)&As[nb][lk + 8][lm] = a1;
            *(float4*)&Bs[nb][lk][lm]     = b0;
            *(float4*)&Bs[nb][lk + 8][lm] = b1;
        }
        __syncthreads();
    }

    // epilogue
    #pragma unroll
    for (int ii = 0; ii < 8; ++ii) {
        int mi = ty * 4 + (ii & 3) + (ii >> 2) * 64;
        float* Crow = Cout + (size_t)(bi + mi) * ldc + bj;
        float4 v0 = {acc[ii][0], acc[ii][1], acc[ii][2], acc[ii][3]};
        float4 v1 = {acc[ii][4], acc[ii][5], acc[ii][6], acc[ii][7]};
        *(float4*)(Crow + tx * 4)      = v0;
        *(float4*)(Crow + tx * 4 + 64) = v1;
    }
}

// ---------------------------------------------------------------------------
// row softmax: S[row, :] = softmax(logits[row, :] + bias)
// ---------------------------------------------------------------------------
__global__ void k_softmax(const float* __restrict__ logits,
                          const float* __restrict__ bias) {
    const int row = blockIdx.x;
    const int tid = threadIdx.x;             // 256
    const float* L = logits + (size_t)row * C_;
    float* Srow = g_S + (size_t)row * C_;

    float v[24];
    float mx = -1e30f;
    #pragma unroll
    for (int i = 0; i < 24; ++i) {
        int j = tid + i * 256;
        v[i] = L[j] + bias[j];
        mx = fmaxf(mx, v[i]);
    }
    __shared__ float red[256];
    red[tid] = mx; __syncthreads();
    for (int s = 128; s > 0; s >>= 1) {
        if (tid < s) red[tid] = fmaxf(red[tid], red[tid + s]);
        __syncthreads();
    }
    mx = red[0];
    __syncthreads();

    float sm = 0.f;
    #pragma unroll
    for (int i = 0; i < 24; ++i) { v[i] = expf(v[i] - mx); sm += v[i]; }
    red[tid] = sm; __syncthreads();
    for (int s = 128; s > 0; s >>= 1) {
        if (tid < s) red[tid] += red[tid + s];
        __syncthreads();
    }
    const float inv = 1.0f / red[0];
    #pragma unroll
    for (int i = 0; i < 24; ++i)
        Srow[tid + i * 256] = v[i] * inv;
}

// ---------------------------------------------------------------------------
// mark adjacency bits (dedup happens naturally; final bitmap is deterministic)
// ---------------------------------------------------------------------------
__global__ void k_mark(const int* __restrict__ ei, int E) {
    int e = blockIdx.x * blockDim.x + threadIdx.x;
    if (e >= E) return;
    unsigned r = (unsigned)ei[e];
    unsigned c = (unsigned)ei[E + e];
    unsigned idx = r * (unsigned)N_ + c;
    atomicOr(&g_bm[idx >> 5], 1u << (idx & 31u));
}

// ---------------------------------------------------------------------------
// T[r, :] = sum_{c : A[r,c]=1} S[c, :]   (bitmap SpMM; ascending c -> deterministic)
// grid: (C/512, N), block 128, each thread owns one float4 of columns
// ---------------------------------------------------------------------------
__global__ void k_spmm() {
    __shared__ unsigned sw[BMW];
    const int r = blockIdx.y;
    const int tid = threadIdx.x;   // 128
    for (int w = tid; w < BMW; w += 128) sw[w] = g_bm[r * BMW + w];
    __syncthreads();

    const int j = (blockIdx.x * 128 + tid) * 4;
    float4 acc = {0.f, 0.f, 0.f, 0.f};
    for (int w = 0; w < BMW; ++w) {
        unsigned bits = sw[w];
        while (bits) {
            int b = __ffs(bits) - 1;
            bits &= bits - 1;
            int c = w * 32 + b;
            const float4 v = *(const float4*)&g_S[(size_t)c * C_ + j];
            acc.x += v.x; acc.y += v.y; acc.z += v.z; acc.w += v.w;
        }
    }
    *(float4*)&g_T[(size_t)r * C_ + j] = acc;
}

// ---------------------------------------------------------------------------
// column sums of S, two-phase (deterministic)
// ---------------------------------------------------------------------------
__global__ void k_colsum_part() {
    const int j  = blockIdx.x * 256 + threadIdx.x;
    const int nc = blockIdx.y;                 // 8 chunks of 1536 rows
    const int n0 = nc * (N_ / 8), n1 = n0 + (N_ / 8);
    float s = 0.f;
    for (int n = n0; n < n1; ++n) s += g_S[(size_t)n * C_ + j];
    g_part[(size_t)nc * C_ + j] = s;
}
__global__ void k_colsum_final(float* __restrict__ out) {
    const int j = blockIdx.x * 256 + threadIdx.x;
    float s = 0.f;
    #pragma unroll
    for (int nc = 0; nc < 8; ++nc) s += g_part[(size_t)nc * C_ + j];
    out[j] = s;
}

// ---------------------------------------------------------------------------
// batch max + tail (perm, batch_pool)
// ---------------------------------------------------------------------------
__global__ void k_bmax(const int* __restrict__ batch) {
    int n = blockIdx.x * blockDim.x + threadIdx.x;
    if (n < N_) atomicMax(&g_maxbatch, batch[n]);
}
__global__ void k_tail(float* __restrict__ perm_out, float* __restrict__ batch_out) {
    int i = blockIdx.x * blockDim.x + threadIdx.x;
    if (i < C_) {
        perm_out[i]  = (float)i;
        batch_out[i] = (float)g_maxbatch;
    }
}

// ---------------------------------------------------------------------------
// launch
// ---------------------------------------------------------------------------
extern "C" void kernel_launch(void* const* d_in, const int* in_sizes, int n_in,
                              void* d_out, int out_size) {
    const float* x     = (const float*)d_in[0];
    const int*   ei    = (const int*)  d_in[1];
    const int*   batch = (const int*)  d_in[2];
    const float* emb   = (const float*)d_in[3];
    const float* W     = (const float*)d_in[4];
    const float* bias  = (const float*)d_in[5];
    float* out = (float*)d_out;
    const int E = in_sizes[1] / 2;

    float *Sp, *Tp, *xTp;
    cudaGetSymbolAddress((void**)&Sp,  g_S);
    cudaGetSymbolAddress((void**)&Tp,  g_T);
    cudaGetSymbolAddress((void**)&xTp, g_xT);

    const size_t off_xpool = 0;
    const size_t off_adj   = (size_t)C_ * F_;
    const size_t off_perm  = off_adj + (size_t)C_ * C_;
    const size_t off_batch = off_perm + C_;
    const size_t off_ssum  = off_batch + C_;

    // 1) xT = (x + emb)^T
    k_xT<<<dim3(F_ / 32, N_ / 32), dim3(32, 8)>>>(x, emb);
    // 2) logits = xT^T @ W   -> g_T  [N, C]
    k_gemm_tn<<<dim3(C_ / 128, N_ / 128), 256>>>(xTp, N_, W, C_, Tp, C_, F_);
    // 3) S = softmax(logits + b)  -> g_S
    k_softmax<<<N_, 256>>>(Tp, bias);
    // 4) adjacency bitmap
    k_zero<<<(BM_TOTAL + 255) / 256, 256>>>();
    k_mark<<<(E + 255) / 256, 256>>>(ei, E);
    // 5) T = A @ S   (overwrites logits; softmax already consumed them)
    k_spmm<<<dim3(C_ / 512, N_), 128>>>();
    // 6) x_pool = S^T @ x   [C, F]
    k_gemm_tn<<<dim3(F_ / 128, C_ / 128), 256>>>(Sp, C_, x, F_, out + off_xpool, F_, N_);
    // 7) adj_pool = S^T @ T  [C, C]   (dominant GEMM, 928 GFLOP)
    k_gemm_tn<<<dim3(C_ / 128, C_ / 128), 256>>>(Sp, C_, Tp, C_, out + off_adj, C_, N_);
    // 8) s_sum = S.sum(axis=0)
    k_colsum_part<<<dim3(C_ / 256, 8), 256>>>();
    k_colsum_final<<<C_ / 256, 256>>>(out + off_ssum);
    // 9) batch_pool = max(batch) broadcast (S > 0 everywhere), perm = arange
    k_bmax<<<(N_ + 255) / 256, 256>>>(batch);
    k_tail<<<(C_ + 255) / 256, 256>>>(out + off_perm, out + off_batch);

    (void)n_in; (void)out_size;
}

// round 3
// speedup vs baseline: 2.1607x; 2.1607x over previous
#include <cuda_runtime.h>
#include <math.h>

// Problem constants (fixed by the dataset)
#define N_  12288
#define F_  256
#define C_  6144
#define BMW (N_ / 32)          // bitmap words per row = 384
#define BM_TOTAL (N_ * BMW)    // 4,718,592 words = 18.9 MB

// ---- scratch (device globals; no runtime allocation allowed) ----
__device__ float    g_S [(size_t)N_ * C_];   // softmax assignments  [N, C]
__device__ float    g_T [(size_t)N_ * C_];   // logits, then A@S     [N, C]
__device__ float    g_xT[(size_t)F_ * N_];   // (x+emb)^T            [F, N]
__device__ unsigned g_bm[BM_TOTAL];          // dedup adjacency bitmap
__device__ float    g_part[8 * C_];          // partial column sums
__device__ int      g_maxbatch;

// ---------------------------------------------------------------------------
// zero scratch that must be clean each launch
// ---------------------------------------------------------------------------
__global__ void k_zero() {
    int i = blockIdx.x * blockDim.x + threadIdx.x;
    if (i < BM_TOTAL) g_bm[i] = 0u;
    if (i == 0) g_maxbatch = 0;
}

// ---------------------------------------------------------------------------
// xT[f, n] = x[n, f] + emb[f]   (tiled transpose)
// ---------------------------------------------------------------------------
__global__ void k_xT(const float* __restrict__ x, const float* __restrict__ emb) {
    __shared__ float tile[32][33];
    int f0 = blockIdx.x * 32, n0 = blockIdx.y * 32;
    int tx = threadIdx.x, ty = threadIdx.y;  // (32, 8)
    #pragma unroll
    for (int i = ty; i < 32; i += 8)
        tile[i][tx] = x[(size_t)(n0 + i) * F_ + f0 + tx] + emb[f0 + tx];
    __syncthreads();
    #pragma unroll
    for (int i = ty; i < 32; i += 8)
        g_xT[(size_t)(f0 + i) * N_ + n0 + tx] = tile[tx][i];
}

// ---------------------------------------------------------------------------
// fp32 SIMT TN GEMM (kept for the small, cancellation-sensitive GEMMs)
// Out[i, j] = sum_k A[k, i] * B[k, j]
// ---------------------------------------------------------------------------
__global__ __launch_bounds__(256, 2)
void k_gemm_tn(const float* __restrict__ A, int lda,
               const float* __restrict__ B, int ldb,
               float* __restrict__ Cout, int ldc, int K) {
    __shared__ float As[2][16][128];
    __shared__ float Bs[2][16][128];

    const int bi = blockIdx.y * 128;
    const int bj = blockIdx.x * 128;
    const int tid = threadIdx.x;
    const int lk  = tid >> 5;
    const int lm  = (tid & 31) << 2;
    const int tx  = tid & 15, ty = tid >> 4;

    const float* Ap = A + (size_t)lk * lda + bi + lm;
    const float* Bp = B + (size_t)lk * ldb + bj + lm;

    float acc[8][8];
    #pragma unroll
    for (int i = 0; i < 8; ++i)
        #pragma unroll
        for (int j = 0; j < 8; ++j) acc[i][j] = 0.f;

    {
        float4 a0 = *(const float4*)(Ap);
        float4 a1 = *(const float4*)(Ap + (size_t)8 * lda);
        float4 b0 = *(const float4*)(Bp);
        float4 b1 = *(const float4*)(Bp + (size_t)8 * ldb);
        *(float4*)&As[0][lk][lm]     = a0;
        *(float4*)&As[0][lk + 8][lm] = a1;
        *(float4*)&Bs[0][lk][lm]     = b0;
        *(float4*)&Bs[0][lk + 8][lm] = b1;
    }
    __syncthreads();

    const int ntiles = K >> 4;
    for (int t = 0; t < ntiles; ++t) {
        float4 a0, a1, b0, b1;
        const bool more = (t + 1 < ntiles);
        if (more) {
            const float* Ap2 = Ap + (size_t)(t + 1) * 16 * lda;
            const float* Bp2 = Bp + (size_t)(t + 1) * 16 * ldb;
            a0 = *(const float4*)(Ap2);
            a1 = *(const float4*)(Ap2 + (size_t)8 * lda);
            b0 = *(const float4*)(Bp2);
            b1 = *(const float4*)(Bp2 + (size_t)8 * ldb);
        }
        const int buf = t & 1;
        #pragma unroll
        for (int k = 0; k < 16; ++k) {
            float4 ra0 = *(const float4*)&As[buf][k][ty * 4];
            float4 ra1 = *(const float4*)&As[buf][k][ty * 4 + 64];
            float4 rb0 = *(const float4*)&Bs[buf][k][tx * 4];
            float4 rb1 = *(const float4*)&Bs[buf][k][tx * 4 + 64];
            float av[8] = {ra0.x, ra0.y, ra0.z, ra0.w, ra1.x, ra1.y, ra1.z, ra1.w};
            float bv[8] = {rb0.x, rb0.y, rb0.z, rb0.w, rb1.x, rb1.y, rb1.z, rb1.w};
            #pragma unroll
            for (int ii = 0; ii < 8; ++ii)
                #pragma unroll
                for (int jj = 0; jj < 8; ++jj)
                    acc[ii][jj] += av[ii] * bv[jj];
        }
        if (more) {
            const int nb = buf ^ 1;
            *(float4*)&As[nb][lk][lm]     = a0;
            *(float4*)&As[nb][lk + 8][lm] = a1;
            *(float4*)&Bs[nb][lk][lm]     = b0;
            *(float4*)&Bs[nb][lk + 8][lm] = b1;
        }
        __syncthreads();
    }

    #pragma unroll
    for (int ii = 0; ii < 8; ++ii) {
        int mi = ty * 4 + (ii & 3) + (ii >> 2) * 64;
        float* Crow = Cout + (size_t)(bi + mi) * ldc + bj;
        float4 v0 = {acc[ii][0], acc[ii][1], acc[ii][2], acc[ii][3]};
        float4 v1 = {acc[ii][4], acc[ii][5], acc[ii][6], acc[ii][7]};
        *(float4*)(Crow + tx * 4)      = v0;
        *(float4*)(Crow + tx * 4 + 64) = v1;
    }
}

// ---------------------------------------------------------------------------
// tf32 tensor-core TN GEMM (for the all-positive-summand adj_pool GEMM)
//   Out[i, j] = sum_k A[k, i] * B[k, j]
//   128x128 block, 8 warps (2 x 4), warp tile 64x32, k-step 16, double buffer.
//   smem k-major with pad 136 (136 % 32 == 8 -> fragment loads conflict-free).
// ---------------------------------------------------------------------------
#define TPAD 136

__device__ __forceinline__ float tf32r(float x) {
    unsigned u;
    asm("cvt.rna.tf32.f32 %0, %1;" : "=r"(u) : "f"(x));
    return __uint_as_float(u);
}

__device__ __forceinline__ void mma_tf32(float* c, const unsigned* a, const unsigned* b) {
    asm volatile(
        "mma.sync.aligned.m16n8k8.row.col.f32.tf32.tf32.f32 "
        "{%0,%1,%2,%3}, {%4,%5,%6,%7}, {%8,%9}, {%0,%1,%2,%3};\n"
        : "+f"(c[0]), "+f"(c[1]), "+f"(c[2]), "+f"(c[3])
        : "r"(a[0]), "r"(a[1]), "r"(a[2]), "r"(a[3]), "r"(b[0]), "r"(b[1]));
}

__global__ __launch_bounds__(256)
void k_gemm_tf32(const float* __restrict__ A, int lda,
                 const float* __restrict__ B, int ldb,
                 float* __restrict__ Cout, int ldc, int K) {
    __shared__ float As[2][16][TPAD];
    __shared__ float Bs[2][16][TPAD];

    const int bi = blockIdx.y * 128;
    const int bj = blockIdx.x * 128;
    const int tid  = threadIdx.x;
    const int warp = tid >> 5, lane = tid & 31;
    const int wm = (warp >> 2) * 64;      // 0 / 64
    const int wn = (warp & 3) * 32;       // 0 / 32 / 64 / 96
    const int g  = lane >> 2;             // group id   0..7
    const int tg = lane & 3;              // thread-in-group 0..3

    // global tile loaders (256 threads cover 16x128 per operand)
    const int lk = tid >> 5;              // 0..7
    const int lm = (tid & 31) << 2;       // float4 column
    const float* Ap = A + (size_t)lk * lda + bi + lm;
    const float* Bp = B + (size_t)lk * ldb + bj + lm;

    float acc[4][4][4];                   // [mi][ni][c0..c3]
    #pragma unroll
    for (int mi = 0; mi < 4; ++mi)
        #pragma unroll
        for (int ni = 0; ni < 4; ++ni)
            #pragma unroll
            for (int c = 0; c < 4; ++c) acc[mi][ni][c] = 0.f;

    // prologue: tile 0 (convert to tf32 on store)
    {
        float4 a0 = *(const float4*)(Ap);
        float4 a1 = *(const float4*)(Ap + (size_t)8 * lda);
        float4 b0 = *(const float4*)(Bp);
        float4 b1 = *(const float4*)(Bp + (size_t)8 * ldb);
        float4 v;
        v = a0; v.x=tf32r(v.x); v.y=tf32r(v.y); v.z=tf32r(v.z); v.w=tf32r(v.w);
        *(float4*)&As[0][lk][lm] = v;
        v = a1; v.x=tf32r(v.x); v.y=tf32r(v.y); v.z=tf32r(v.z); v.w=tf32r(v.w);
        *(float4*)&As[0][lk + 8][lm] = v;
        v = b0; v.x=tf32r(v.x); v.y=tf32r(v.y); v.z=tf32r(v.z); v.w=tf32r(v.w);
        *(float4*)&Bs[0][lk][lm] = v;
        v = b1; v.x=tf32r(v.x); v.y=tf32r(v.y); v.z=tf32r(v.z); v.w=tf32r(v.w);
        *(float4*)&Bs[0][lk + 8][lm] = v;
    }
    __syncthreads();

    const int ntiles = K >> 4;
    for (int t = 0; t < ntiles; ++t) {
        float4 pa0, pa1, pb0, pb1;
        const bool more = (t + 1 < ntiles);
        if (more) {
            const float* Ap2 = Ap + (size_t)(t + 1) * 16 * lda;
            const float* Bp2 = Bp + (size_t)(t + 1) * 16 * ldb;
            pa0 = *(const float4*)(Ap2);
            pa1 = *(const float4*)(Ap2 + (size_t)8 * lda);
            pb0 = *(const float4*)(Bp2);
            pb1 = *(const float4*)(Bp2 + (size_t)8 * ldb);
        }
        const int buf = t & 1;

        #pragma unroll
        for (int kb = 0; kb < 16; kb += 8) {
            unsigned af[4][4];   // [mi][a0..a3]
            unsigned bf[4][2];   // [ni][b0..b1]
            #pragma unroll
            for (int mi = 0; mi < 4; ++mi) {
                const int m0 = wm + mi * 16 + g;
                af[mi][0] = __float_as_uint(As[buf][kb + tg][m0]);
                af[mi][1] = __float_as_uint(As[buf][kb + tg][m0 + 8]);
                af[mi][2] = __float_as_uint(As[buf][kb + tg + 4][m0]);
                af[mi][3] = __float_as_uint(As[buf][kb + tg + 4][m0 + 8]);
            }
            #pragma unroll
            for (int ni = 0; ni < 4; ++ni) {
                const int n0 = wn + ni * 8 + g;
                bf[ni][0] = __float_as_uint(Bs[buf][kb + tg][n0]);
                bf[ni][1] = __float_as_uint(Bs[buf][kb + tg + 4][n0]);
            }
            #pragma unroll
            for (int mi = 0; mi < 4; ++mi)
                #pragma unroll
                for (int ni = 0; ni < 4; ++ni)
                    mma_tf32(acc[mi][ni], af[mi], bf[ni]);
        }

        if (more) {
            const int nb = buf ^ 1;
            float4 v;
            v = pa0; v.x=tf32r(v.x); v.y=tf32r(v.y); v.z=tf32r(v.z); v.w=tf32r(v.w);
            *(float4*)&As[nb][lk][lm] = v;
            v = pa1; v.x=tf32r(v.x); v.y=tf32r(v.y); v.z=tf32r(v.z); v.w=tf32r(v.w);
            *(float4*)&As[nb][lk + 8][lm] = v;
            v = pb0; v.x=tf32r(v.x); v.y=tf32r(v.y); v.z=tf32r(v.z); v.w=tf32r(v.w);
            *(float4*)&Bs[nb][lk][lm] = v;
            v = pb1; v.x=tf32r(v.x); v.y=tf32r(v.y); v.z=tf32r(v.z); v.w=tf32r(v.w);
            *(float4*)&Bs[nb][lk + 8][lm] = v;
        }
        __syncthreads();
    }

    // epilogue: c0 (g, 2tg) c1 (g, 2tg+1) c2 (g+8, 2tg) c3 (g+8, 2tg+1)
    #pragma unroll
    for (int mi = 0; mi < 4; ++mi) {
        #pragma unroll
        for (int ni = 0; ni < 4; ++ni) {
            const int r0 = bi + wm + mi * 16 + g;
            const int cc = bj + wn + ni * 8 + tg * 2;
            float2 v0 = {acc[mi][ni][0], acc[mi][ni][1]};
            float2 v1 = {acc[mi][ni][2], acc[mi][ni][3]};
            *(float2*)(Cout + (size_t)r0 * ldc + cc)       = v0;
            *(float2*)(Cout + (size_t)(r0 + 8) * ldc + cc) = v1;
        }
    }
}

// ---------------------------------------------------------------------------
// row softmax: S[row, :] = softmax(logits[row, :] + bias)
// ---------------------------------------------------------------------------
__global__ void k_softmax(const float* __restrict__ logits,
                          const float* __restrict__ bias) {
    const int row = blockIdx.x;
    const int tid = threadIdx.x;             // 256
    const float* L = logits + (size_t)row * C_;
    float* Srow = g_S + (size_t)row * C_;

    float v[24];
    float mx = -1e30f;
    #pragma unroll
    for (int i = 0; i < 24; ++i) {
        int j = tid + i * 256;
        v[i] = L[j] + bias[j];
        mx = fmaxf(mx, v[i]);
    }
    __shared__ float red[256];
    red[tid] = mx; __syncthreads();
    for (int s = 128; s > 0; s >>= 1) {
        if (tid < s) red[tid] = fmaxf(red[tid], red[tid + s]);
        __syncthreads();
    }
    mx = red[0];
    __syncthreads();

    float sm = 0.f;
    #pragma unroll
    for (int i = 0; i < 24; ++i) { v[i] = expf(v[i] - mx); sm += v[i]; }
    red[tid] = sm; __syncthreads();
    for (int s = 128; s > 0; s >>= 1) {
        if (tid < s) red[tid] += red[tid + s];
        __syncthreads();
    }
    const float inv = 1.0f / red[0];
    #pragma unroll
    for (int i = 0; i < 24; ++i)
        Srow[tid + i * 256] = v[i] * inv;
}

// ---------------------------------------------------------------------------
// mark adjacency bits (dedup happens naturally; final bitmap is deterministic)
// ---------------------------------------------------------------------------
__global__ void k_mark(const int* __restrict__ ei, int E) {
    int e = blockIdx.x * blockDim.x + threadIdx.x;
    if (e >= E) return;
    unsigned r = (unsigned)ei[e];
    unsigned c = (unsigned)ei[E + e];
    unsigned idx = r * (unsigned)N_ + c;
    atomicOr(&g_bm[idx >> 5], 1u << (idx & 31u));
}

// ---------------------------------------------------------------------------
// T[r, :] = sum_{c : A[r,c]=1} S[c, :]   (bitmap SpMM; ascending c -> deterministic)
// ---------------------------------------------------------------------------
__global__ void k_spmm() {
    __shared__ unsigned sw[BMW];
    const int r = blockIdx.y;
    const int tid = threadIdx.x;   // 128
    for (int w = tid; w < BMW; w += 128) sw[w] = g_bm[r * BMW + w];
    __syncthreads();

    const int j = (blockIdx.x * 128 + tid) * 4;
    float4 acc = {0.f, 0.f, 0.f, 0.f};
    for (int w = 0; w < BMW; ++w) {
        unsigned bits = sw[w];
        while (bits) {
            int b = __ffs(bits) - 1;
            bits &= bits - 1;
            int c = w * 32 + b;
            const float4 v = *(const float4*)&g_S[(size_t)c * C_ + j];
            acc.x += v.x; acc.y += v.y; acc.z += v.z; acc.w += v.w;
        }
    }
    *(float4*)&g_T[(size_t)r * C_ + j] = acc;
}

// ---------------------------------------------------------------------------
// column sums of S, two-phase (deterministic)
// ---------------------------------------------------------------------------
__global__ void k_colsum_part() {
    const int j  = blockIdx.x * 256 + threadIdx.x;
    const int nc = blockIdx.y;
    const int n0 = nc * (N_ / 8), n1 = n0 + (N_ / 8);
    float s = 0.f;
    for (int n = n0; n < n1; ++n) s += g_S[(size_t)n * C_ + j];
    g_part[(size_t)nc * C_ + j] = s;
}
__global__ void k_colsum_final(float* __restrict__ out) {
    const int j = blockIdx.x * 256 + threadIdx.x;
    float s = 0.f;
    #pragma unroll
    for (int nc = 0; nc < 8; ++nc) s += g_part[(size_t)nc * C_ + j];
    out[j] = s;
}

// ---------------------------------------------------------------------------
// batch max + tail (perm, batch_pool)
// ---------------------------------------------------------------------------
__global__ void k_bmax(const int* __restrict__ batch) {
    int n = blockIdx.x * blockDim.x + threadIdx.x;
    if (n < N_) atomicMax(&g_maxbatch, batch[n]);
}
__global__ void k_tail(float* __restrict__ perm_out, float* __restrict__ batch_out) {
    int i = blockIdx.x * blockDim.x + threadIdx.x;
    if (i < C_) {
        perm_out[i]  = (float)i;
        batch_out[i] = (float)g_maxbatch;
    }
}

// ---------------------------------------------------------------------------
// launch
// ---------------------------------------------------------------------------
extern "C" void kernel_launch(void* const* d_in, const int* in_sizes, int n_in,
                              void* d_out, int out_size) {
    const float* x     = (const float*)d_in[0];
    const int*   ei    = (const int*)  d_in[1];
    const int*   batch = (const int*)  d_in[2];
    const float* emb   = (const float*)d_in[3];
    const float* W     = (const float*)d_in[4];
    const float* bias  = (const float*)d_in[5];
    float* out = (float*)d_out;
    const int E = in_sizes[1] / 2;

    float *Sp, *Tp, *xTp;
    cudaGetSymbolAddress((void**)&Sp,  g_S);
    cudaGetSymbolAddress((void**)&Tp,  g_T);
    cudaGetSymbolAddress((void**)&xTp, g_xT);

    const size_t off_xpool = 0;
    const size_t off_adj   = (size_t)C_ * F_;
    const size_t off_perm  = off_adj + (size_t)C_ * C_;
    const size_t off_batch = off_perm + C_;
    const size_t off_ssum  = off_batch + C_;

    // 1) xT = (x + emb)^T
    k_xT<<<dim3(F_ / 32, N_ / 32), dim3(32, 8)>>>(x, emb);
    // 2) logits = xT^T @ W   -> g_T  [N, C]   (fp32: feeds softmax)
    k_gemm_tn<<<dim3(C_ / 128, N_ / 128), 256>>>(xTp, N_, W, C_, Tp, C_, F_);
    // 3) S = softmax(logits + b)  -> g_S
    k_softmax<<<N_, 256>>>(Tp, bias);
    // 4) adjacency bitmap
    k_zero<<<(BM_TOTAL + 255) / 256, 256>>>();
    k_mark<<<(E + 255) / 256, 256>>>(ei, E);
    // 5) T = A @ S   (overwrites logits; softmax already consumed them)
    k_spmm<<<dim3(C_ / 512, N_), 128>>>();
    // 6) x_pool = S^T @ x   [C, F]   (fp32: mixed-sign cancellation)
    k_gemm_tn<<<dim3(F_ / 128, C_ / 128), 256>>>(Sp, C_, x, F_, out + off_xpool, F_, N_);
    // 7) adj_pool = S^T @ T  [C, C]  (dominant GEMM -> tf32 tensor cores;
    //    all-positive summands, rna rounding -> error averages out)
    k_gemm_tf32<<<dim3(C_ / 128, C_ / 128), 256>>>(Sp, C_, Tp, C_, out + off_adj, C_, N_);
    // 8) s_sum = S.sum(axis=0)
    k_colsum_part<<<dim3(C_ / 256, 8), 256>>>();
    k_colsum_final<<<C_ / 256, 256>>>(out + off_ssum);
    // 9) batch_pool = max(batch) broadcast (S > 0 everywhere), perm = arange
    k_bmax<<<(N_ + 255) / 256, 256>>>(batch);
    k_tail<<<(C_ + 255) / 256, 256>>>(out + off_perm, out + off_batch);

    (void)n_in; (void)out_size;
}

// round 6
// speedup vs baseline: 3.1074x; 1.4382x over previous
#include <cuda_runtime.h>
#include <cuda_bf16.h>
#include <math.h>
#include <stdint.h>

// Problem constants (fixed by the dataset)
#define N_  12288
#define F_  256
#define C_  6144
#define BMW (N_ / 32)
#define BM_TOTAL (N_ * BMW)

// ---- scratch (device globals; no runtime allocation allowed) ----
__device__ float    g_S [(size_t)N_ * C_];                 // softmax S [N, C]
__device__ float    g_T [(size_t)N_ * C_];                 // logits, then A@S [N, C]
__device__ float    g_xT[(size_t)F_ * N_];                 // (x+emb)^T [F, N]
__device__ __align__(128) __nv_bfloat16 g_SbT[(size_t)C_ * N_];  // S^T bf16 [C, N]
__device__ __align__(128) __nv_bfloat16 g_TbT[(size_t)C_ * N_];  // T^T bf16 [C, N]
__device__ unsigned g_bm[BM_TOTAL];
__device__ float    g_part[8 * C_];
__device__ int      g_maxbatch;

// ===========================================================================
// PTX helpers (sm_80-era ISA only: the harness lowers PTX at compute_103,
// which rejects tcgen05/TMEM; ldmatrix + mma.sync + cp.async are supported)
// ===========================================================================
__device__ __forceinline__ uint32_t smem_u32(const void* p) {
    uint32_t a;
    asm("{ .reg .u64 t; cvta.to.shared.u64 t, %1; cvt.u32.u64 %0, t; }" : "=r"(a) : "l"(p));
    return a;
}
__device__ __forceinline__ void cpa16(uint32_t dst, const void* src) {
    asm volatile("cp.async.cg.shared.global [%0], [%1], 16;" :: "r"(dst), "l"(src));
}
#define CPA_COMMIT() asm volatile("cp.async.commit_group;" ::: "memory")
#define CPA_WAIT3()  asm volatile("cp.async.wait_group 3;" ::: "memory")

__device__ __forceinline__ void ldsm_x4(uint32_t* r, uint32_t addr) {
    asm volatile("ldmatrix.sync.aligned.m8n8.x4.shared.b16 {%0,%1,%2,%3}, [%4];"
                 : "=r"(r[0]), "=r"(r[1]), "=r"(r[2]), "=r"(r[3]) : "r"(addr));
}
__device__ __forceinline__ void mma_bf16(float* c, const uint32_t* a, const uint32_t* b) {
    asm volatile(
        "mma.sync.aligned.m16n8k16.row.col.f32.bf16.bf16.f32 "
        "{%0,%1,%2,%3}, {%4,%5,%6,%7}, {%8,%9}, {%0,%1,%2,%3};\n"
        : "+f"(c[0]), "+f"(c[1]), "+f"(c[2]), "+f"(c[3])
        : "r"(a[0]), "r"(a[1]), "r"(a[2]), "r"(a[3]), "r"(b[0]), "r"(b[1]));
}

// ===========================================================================
// bf16 mma.sync GEMM for adj_pool: Out[i,j] = sum_k SbT[i][k] * TbT[j][k]
//   Block 128x128, 8 warps (2x4), warp tile 64x32, K-step 32, 4-stage cp.async.
//   smem rows: 32 bf16 = 64B data, stride 80B (5x16B -> ldmatrix conflict-free).
// ===========================================================================
#define ROWB        80
#define TILE_BYTES  (128 * ROWB)       // 10240
#define STAGE_BYTES (2 * TILE_BYTES)   // 20480 (A + B)
#define STG         4
#define ADJ_SMEM    (STG * STAGE_BYTES) // 81920
#define NSTAGES     (N_ / 32)          // 384

__device__ __forceinline__ void adj_load_stage(uint32_t smb, int st, int s,
                                               const __nv_bfloat16* Sb,
                                               const __nv_bfloat16* Tb,
                                               int bi, int bj, int tid) {
    const int kbase = s * 32;
    const uint32_t stA = smb + st * STAGE_BYTES;
    const uint32_t stB = stA + TILE_BYTES;
    #pragma unroll
    for (int r = 0; r < 2; ++r) {
        int i = tid + r * 256;
        int row = i >> 2, cc = i & 3;
        cpa16(stA + row * ROWB + cc * 16,
              Sb + (size_t)(bi + row) * N_ + kbase + cc * 8);
    }
    #pragma unroll
    for (int r = 0; r < 2; ++r) {
        int i = tid + r * 256;
        int row = i >> 2, cc = i & 3;
        cpa16(stB + row * ROWB + cc * 16,
              Tb + (size_t)(bj + row) * N_ + kbase + cc * 8);
    }
}

__global__ __launch_bounds__(256, 2)
void k_adj_bf16(const __nv_bfloat16* __restrict__ Sb,
                const __nv_bfloat16* __restrict__ Tb,
                float* __restrict__ Cout) {
    extern __shared__ char smem[];
    const uint32_t smb = smem_u32(smem);
    const int tid = threadIdx.x, warp = tid >> 5, lane = tid & 31;
    const int bi = blockIdx.y * 128;
    const int bj = blockIdx.x * 128;
    const int wm = (warp >> 2) * 64;    // 0 / 64
    const int wn = (warp & 3) * 32;     // 0 / 32 / 64 / 96

    float acc[4][4][4];
    #pragma unroll
    for (int mi = 0; mi < 4; ++mi)
        #pragma unroll
        for (int ni = 0; ni < 4; ++ni)
            #pragma unroll
            for (int c = 0; c < 4; ++c) acc[mi][ni][c] = 0.f;

    // prologue: stages 0..STG-2
    #pragma unroll
    for (int s = 0; s < STG - 1; ++s) {
        adj_load_stage(smb, s, s, Sb, Tb, bi, bj, tid);
        CPA_COMMIT();
    }

    // precomputed intra-warp fragment offsets
    const uint32_t aLaneOff = (uint32_t)((wm + (lane & 15)) * ROWB + (lane >> 4) * 16);
    const uint32_t bLaneOff = (uint32_t)((wn + (lane & 7) + ((lane >> 4) & 1) * 8) * ROWB
                                         + ((lane >> 3) & 1) * 16);

    for (int s = 0; s < NSTAGES; ++s) {
        if (s + STG - 1 < NSTAGES)
            adj_load_stage(smb, (s + STG - 1) % STG, s + STG - 1, Sb, Tb, bi, bj, tid);
        CPA_COMMIT();
        CPA_WAIT3();
        __syncthreads();

        const uint32_t curA = smb + (s % STG) * STAGE_BYTES;
        const uint32_t curB = curA + TILE_BYTES;

        #pragma unroll
        for (int k16 = 0; k16 < 2; ++k16) {
            uint32_t a[4][4], b[4][2];
            #pragma unroll
            for (int mi = 0; mi < 4; ++mi)
                ldsm_x4(a[mi], curA + aLaneOff + (uint32_t)(mi * 16 * ROWB + k16 * 32));
            #pragma unroll
            for (int nh = 0; nh < 2; ++nh) {
                uint32_t r[4];
                ldsm_x4(r, curB + bLaneOff + (uint32_t)(nh * 16 * ROWB + k16 * 32));
                b[2 * nh][0] = r[0]; b[2 * nh][1] = r[1];
                b[2 * nh + 1][0] = r[2]; b[2 * nh + 1][1] = r[3];
            }
            #pragma unroll
            for (int mi = 0; mi < 4; ++mi)
                #pragma unroll
                for (int ni = 0; ni < 4; ++ni)
                    mma_bf16(acc[mi][ni], a[mi], b[ni]);
        }
        __syncthreads();
    }

    // epilogue: c0,c1 -> (row, col..col+1); c2,c3 -> (row+8, ...)
    #pragma unroll
    for (int mi = 0; mi < 4; ++mi) {
        #pragma unroll
        for (int ni = 0; ni < 4; ++ni) {
            const int row = bi + wm + mi * 16 + (lane >> 2);
            const int col = bj + wn + ni * 8 + (lane & 3) * 2;
            float2 v0 = {acc[mi][ni][0], acc[mi][ni][1]};
            float2 v1 = {acc[mi][ni][2], acc[mi][ni][3]};
            *(float2*)(Cout + (size_t)row * C_ + col)       = v0;
            *(float2*)(Cout + (size_t)(row + 8) * C_ + col) = v1;
        }
    }
}

// ===========================================================================
// transpose fp32 [N_, C_] -> bf16 [C_, N_]
// ===========================================================================
__global__ void k_tr_bf16(const float* __restrict__ src, __nv_bfloat16* __restrict__ dst) {
    __shared__ float tile[32][33];
    int c0 = blockIdx.x * 32, k0 = blockIdx.y * 32;
    int tx = threadIdx.x, ty = threadIdx.y;   // (32, 8)
    #pragma unroll
    for (int i = ty; i < 32; i += 8)
        tile[i][tx] = src[(size_t)(k0 + i) * C_ + c0 + tx];
    __syncthreads();
    #pragma unroll
    for (int i = ty; i < 32; i += 8)
        dst[(size_t)(c0 + i) * N_ + k0 + tx] = __float2bfloat16(tile[tx][i]);
}

// ===========================================================================
// remaining pipeline (unchanged from R3 baseline)
// ===========================================================================
__global__ void k_zero() {
    int i = blockIdx.x * blockDim.x + threadIdx.x;
    if (i < BM_TOTAL) g_bm[i] = 0u;
    if (i == 0) g_maxbatch = 0;
}

__global__ void k_xT(const float* __restrict__ x, const float* __restrict__ emb) {
    __shared__ float tile[32][33];
    int f0 = blockIdx.x * 32, n0 = blockIdx.y * 32;
    int tx = threadIdx.x, ty = threadIdx.y;
    #pragma unroll
    for (int i = ty; i < 32; i += 8)
        tile[i][tx] = x[(size_t)(n0 + i) * F_ + f0 + tx] + emb[f0 + tx];
    __syncthreads();
    #pragma unroll
    for (int i = ty; i < 32; i += 8)
        g_xT[(size_t)(f0 + i) * N_ + n0 + tx] = tile[tx][i];
}

__global__ __launch_bounds__(256, 2)
void k_gemm_tn(const float* __restrict__ A, int lda,
               const float* __restrict__ B, int ldb,
               float* __restrict__ Cout, int ldc, int K) {
    __shared__ float As[2][16][128];
    __shared__ float Bs[2][16][128];

    const int bi = blockIdx.y * 128;
    const int bj = blockIdx.x * 128;
    const int tid = threadIdx.x;
    const int lk  = tid >> 5;
    const int lm  = (tid & 31) << 2;
    const int tx  = tid & 15, ty = tid >> 4;

    const float* Ap = A + (size_t)lk * lda + bi + lm;
    const float* Bp = B + (size_t)lk * ldb + bj + lm;

    float acc[8][8];
    #pragma unroll
    for (int i = 0; i < 8; ++i)
        #pragma unroll
        for (int j = 0; j < 8; ++j) acc[i][j] = 0.f;

    {
        float4 a0 = *(const float4*)(Ap);
        float4 a1 = *(const float4*)(Ap + (size_t)8 * lda);
        float4 b0 = *(const float4*)(Bp);
        float4 b1 = *(const float4*)(Bp + (size_t)8 * ldb);
        *(float4*)&As[0][lk][lm]     = a0;
        *(float4*)&As[0][lk + 8][lm] = a1;
        *(float4*)&Bs[0][lk][lm]     = b0;
        *(float4*)&Bs[0][lk + 8][lm] = b1;
    }
    __syncthreads();

    const int ntiles = K >> 4;
    for (int t = 0; t < ntiles; ++t) {
        float4 a0, a1, b0, b1;
        const bool more = (t + 1 < ntiles);
        if (more) {
            const float* Ap2 = Ap + (size_t)(t + 1) * 16 * lda;
            const float* Bp2 = Bp + (size_t)(t + 1) * 16 * ldb;
            a0 = *(const float4*)(Ap2);
            a1 = *(const float4*)(Ap2 + (size_t)8 * lda);
            b0 = *(const float4*)(Bp2);
            b1 = *(const float4*)(Bp2 + (size_t)8 * ldb);
        }
        const int buf = t & 1;
        #pragma unroll
        for (int k = 0; k < 16; ++k) {
            float4 ra0 = *(const float4*)&As[buf][k][ty * 4];
            float4 ra1 = *(const float4*)&As[buf][k][ty * 4 + 64];
            float4 rb0 = *(const float4*)&Bs[buf][k][tx * 4];
            float4 rb1 = *(const float4*)&Bs[buf][k][tx * 4 + 64];
            float av[8] = {ra0.x, ra0.y, ra0.z, ra0.w, ra1.x, ra1.y, ra1.z, ra1.w};
            float bv[8] = {rb0.x, rb0.y, rb0.z, rb0.w, rb1.x, rb1.y, rb1.z, rb1.w};
            #pragma unroll
            for (int ii = 0; ii < 8; ++ii)
                #pragma unroll
                for (int jj = 0; jj < 8; ++jj)
                    acc[ii][jj] += av[ii] * bv[jj];
        }
        if (more) {
            const int nb = buf ^ 1;
            *(float4*)&As[nb][lk][lm]     = a0;
            *(float4*)&As[nb][lk + 8][lm] = a1;
            *(float4*)&Bs[nb][lk][lm]     = b0;
            *(float4*)&Bs[nb][lk + 8][lm] = b1;
        }
        __syncthreads();
    }

    #pragma unroll
    for (int ii = 0; ii < 8; ++ii) {
        int mi = ty * 4 + (ii & 3) + (ii >> 2) * 64;
        float* Crow = Cout + (size_t)(bi + mi) * ldc + bj;
        float4 v0 = {acc[ii][0], acc[ii][1], acc[ii][2], acc[ii][3]};
        float4 v1 = {acc[ii][4], acc[ii][5], acc[ii][6], acc[ii][7]};
        *(float4*)(Crow + tx * 4)      = v0;
        *(float4*)(Crow + tx * 4 + 64) = v1;
    }
}

__global__ void k_softmax(const float* __restrict__ logits,
                          const float* __restrict__ bias) {
    const int row = blockIdx.x;
    const int tid = threadIdx.x;
    const float* L = logits + (size_t)row * C_;
    float* Srow = g_S + (size_t)row * C_;

    float v[24];
    float mx = -1e30f;
    #pragma unroll
    for (int i = 0; i < 24; ++i) {
        int j = tid + i * 256;
        v[i] = L[j] + bias[j];
        mx = fmaxf(mx, v[i]);
    }
    __shared__ float red[256];
    red[tid] = mx; __syncthreads();
    for (int s = 128; s > 0; s >>= 1) {
        if (tid < s) red[tid] = fmaxf(red[tid], red[tid + s]);
        __syncthreads();
    }
    mx = red[0];
    __syncthreads();

    float sm = 0.f;
    #pragma unroll
    for (int i = 0; i < 24; ++i) { v[i] = expf(v[i] - mx); sm += v[i]; }
    red[tid] = sm; __syncthreads();
    for (int s = 128; s > 0; s >>= 1) {
        if (tid < s) red[tid] += red[tid + s];
        __syncthreads();
    }
    const float inv = 1.0f / red[0];
    #pragma unroll
    for (int i = 0; i < 24; ++i)
        Srow[tid + i * 256] = v[i] * inv;
}

__global__ void k_mark(const int* __restrict__ ei, int E) {
    int e = blockIdx.x * blockDim.x + threadIdx.x;
    if (e >= E) return;
    unsigned r = (unsigned)ei[e];
    unsigned c = (unsigned)ei[E + e];
    unsigned idx = r * (unsigned)N_ + c;
    atomicOr(&g_bm[idx >> 5], 1u << (idx & 31u));
}

__global__ void k_spmm() {
    __shared__ unsigned sw[BMW];
    const int r = blockIdx.y;
    const int tid = threadIdx.x;
    for (int w = tid; w < BMW; w += 128) sw[w] = g_bm[r * BMW + w];
    __syncthreads();

    const int j = (blockIdx.x * 128 + tid) * 4;
    float4 acc = {0.f, 0.f, 0.f, 0.f};
    for (int w = 0; w < BMW; ++w) {
        unsigned bits = sw[w];
        while (bits) {
            int b = __ffs(bits) - 1;
            bits &= bits - 1;
            int c = w * 32 + b;
            const float4 v = *(const float4*)&g_S[(size_t)c * C_ + j];
            acc.x += v.x; acc.y += v.y; acc.z += v.z; acc.w += v.w;
        }
    }
    *(float4*)&g_T[(size_t)r * C_ + j] = acc;
}

__global__ void k_colsum_part() {
    const int j  = blockIdx.x * 256 + threadIdx.x;
    const int nc = blockIdx.y;
    const int n0 = nc * (N_ / 8), n1 = n0 + (N_ / 8);
    float s = 0.f;
    for (int n = n0; n < n1; ++n) s += g_S[(size_t)n * C_ + j];
    g_part[(size_t)nc * C_ + j] = s;
}
__global__ void k_colsum_final(float* __restrict__ out) {
    const int j = blockIdx.x * 256 + threadIdx.x;
    float s = 0.f;
    #pragma unroll
    for (int nc = 0; nc < 8; ++nc) s += g_part[(size_t)nc * C_ + j];
    out[j] = s;
}

__global__ void k_bmax(const int* __restrict__ batch) {
    int n = blockIdx.x * blockDim.x + threadIdx.x;
    if (n < N_) atomicMax(&g_maxbatch, batch[n]);
}
__global__ void k_tail(float* __restrict__ perm_out, float* __restrict__ batch_out) {
    int i = blockIdx.x * blockDim.x + threadIdx.x;
    if (i < C_) {
        perm_out[i]  = (float)i;
        batch_out[i] = (float)g_maxbatch;
    }
}

// ===========================================================================
// launch
// ===========================================================================
extern "C" void kernel_launch(void* const* d_in, const int* in_sizes, int n_in,
                              void* d_out, int out_size) {
    const float* x     = (const float*)d_in[0];
    const int*   ei    = (const int*)  d_in[1];
    const int*   batch = (const int*)  d_in[2];
    const float* emb   = (const float*)d_in[3];
    const float* W     = (const float*)d_in[4];
    const float* bias  = (const float*)d_in[5];
    float* out = (float*)d_out;
    const int E = in_sizes[1] / 2;

    float *Sp, *Tp, *xTp;
    __nv_bfloat16 *SbTp, *TbTp;
    cudaGetSymbolAddress((void**)&Sp,   g_S);
    cudaGetSymbolAddress((void**)&Tp,   g_T);
    cudaGetSymbolAddress((void**)&xTp,  g_xT);
    cudaGetSymbolAddress((void**)&SbTp, g_SbT);
    cudaGetSymbolAddress((void**)&TbTp, g_TbT);

    cudaFuncSetAttribute(k_adj_bf16, cudaFuncAttributeMaxDynamicSharedMemorySize, ADJ_SMEM);

    const size_t off_xpool = 0;
    const size_t off_adj   = (size_t)C_ * F_;
    const size_t off_perm  = off_adj + (size_t)C_ * C_;
    const size_t off_batch = off_perm + C_;
    const size_t off_ssum  = off_batch + C_;

    // 1) xT = (x + emb)^T
    k_xT<<<dim3(F_ / 32, N_ / 32), dim3(32, 8)>>>(x, emb);
    // 2) logits = xT^T @ W  -> g_T  [N, C]  (fp32: feeds softmax)
    k_gemm_tn<<<dim3(C_ / 128, N_ / 128), 256>>>(xTp, N_, W, C_, Tp, C_, F_);
    // 3) S = softmax(logits + b) -> g_S
    k_softmax<<<N_, 256>>>(Tp, bias);
    // 4) adjacency bitmap
    k_zero<<<(BM_TOTAL + 255) / 256, 256>>>();
    k_mark<<<(E + 255) / 256, 256>>>(ei, E);
    // 5) T = A @ S  (overwrites logits; softmax already consumed them)
    k_spmm<<<dim3(C_ / 512, N_), 128>>>();
    // 6) bf16 transposed copies for the tensor-core GEMM
    k_tr_bf16<<<dim3(C_ / 32, N_ / 32), dim3(32, 8)>>>(Sp, SbTp);
    k_tr_bf16<<<dim3(C_ / 32, N_ / 32), dim3(32, 8)>>>(Tp, TbTp);
    // 7) x_pool = S^T @ x  [C, F]  (fp32 SIMT: mixed-sign cancellation)
    k_gemm_tn<<<dim3(F_ / 128, C_ / 128), 256>>>(Sp, C_, x, F_, out + off_xpool, F_, N_);
    // 8) adj_pool = S^T @ T  [C, C]  -> bf16 mma.sync (all-positive summands)
    k_adj_bf16<<<dim3(C_ / 128, C_ / 128), 256, ADJ_SMEM>>>(SbTp, TbTp, out + off_adj);
    // 9) s_sum = S.sum(axis=0)
    k_colsum_part<<<dim3(C_ / 256, 8), 256>>>();
    k_colsum_final<<<C_ / 256, 256>>>(out + off_ssum);
    // 10) batch_pool = max(batch) broadcast, perm = arange
    k_bmax<<<(N_ + 255) / 256, 256>>>(batch);
    k_tail<<<(C_ + 255) / 256, 256>>>(out + off_perm, out + off_batch);

    (void)n_in; (void)out_size;
}